// round 3
// baseline (speedup 1.0000x reference)
#include <cuda_runtime.h>
#include <stdint.h>

#define NA 262144
#define NG 100
#define GRID 592
#define TPB 256
#define NTH (GRID * TPB)   // 151552

// ----------------- persistent scratch (device globals; no allocation) -----------------
__device__ float              g_max_ov[NA];
__device__ unsigned char      g_inside[NA];
__device__ unsigned char      g_keptA[NA];
__device__ unsigned char      g_keptF[NA];
__device__ unsigned char      g_keptB[NA];
__device__ int                g_ilist[NA];
__device__ int                g_icount;
__device__ int                g_clist[NA];
__device__ int                g_ccount;
__device__ int                g_candlist[8192];
__device__ int                g_candcnt;
__device__ int                g_flist[32768];
__device__ int                g_flcnt;
__device__ int                g_kalist[4096];
__device__ unsigned int       g_gtmax_enc[NG];
__device__ unsigned int       g_histbg[4096];
__device__ int                g_bgcnt[4096];
__device__ unsigned long long g_bgbuf[4096 * 128];
__device__ int                g_bgB;
__device__ unsigned int       g_barcnt;
__device__ volatile unsigned  g_bargen;

// ----------------- JAX threefry2x32 (partitionable path) -----------------
__host__ __device__ inline void tf2x32(unsigned k0, unsigned k1, unsigned x0, unsigned x1,
                                       unsigned &o0, unsigned &o1) {
    unsigned k2 = k0 ^ k1 ^ 0x1BD11BDAu;
    x0 += k0; x1 += k1;
#define RR(r) { x0 += x1; x1 = (x1 << (r)) | (x1 >> (32 - (r))); x1 ^= x0; }
    RR(13) RR(15) RR(26) RR(6)   x0 += k1; x1 += k2 + 1u;
    RR(17) RR(29) RR(16) RR(24)  x0 += k2; x1 += k0 + 2u;
    RR(13) RR(15) RR(26) RR(6)   x0 += k0; x1 += k1 + 3u;
    RR(17) RR(29) RR(16) RR(24)  x0 += k1; x1 += k2 + 4u;
    RR(13) RR(15) RR(26) RR(6)   x0 += k2; x1 += k0 + 5u;
#undef RR
    o0 = x0; o1 = x1;
}

__device__ __forceinline__ unsigned rng_v(unsigned ka, unsigned kb, unsigned i) {
    unsigned a, b; tf2x32(ka, kb, 0u, i, a, b);
    return (a ^ b) >> 9;   // 23-bit; uniform = v * 2^-23 (strictly monotone in v)
}

__device__ __forceinline__ float dec_gtmax(unsigned e) {
    return (e & 0x80000000u) ? __uint_as_float(e & 0x7FFFFFFFu) : __uint_as_float(~e);
}

// ----------------- software grid barrier (all GRID blocks resident) -----------------
__device__ __forceinline__ void gbar() {
    __syncthreads();
    if (threadIdx.x == 0) {
        __threadfence();
        unsigned gen = g_bargen;
        if (atomicAdd(&g_barcnt, 1u) == (unsigned)GRID - 1u) {
            g_barcnt = 0u;
            __threadfence();
            g_bargen = gen + 1u;
        } else {
            while (g_bargen == gen) { }
        }
        __threadfence();
    }
    __syncthreads();
}

// ----------------- block-0 helpers (256 threads) -----------------
// After call: saux[256] = boundary bin B (4096 if total<=k), saux[257] = need within B.
__device__ void find_boundary(unsigned* shist, unsigned* saux, int k) {
    int t = threadIdx.x;
    unsigned csum = 0;
    #pragma unroll
    for (int j = 0; j < 16; j++) csum += shist[t * 16 + j];
    saux[t] = csum;
    __syncthreads();
    for (int o = 1; o < 256; o <<= 1) {
        unsigned add = (t >= o) ? saux[t - o] : 0u;
        __syncthreads();
        saux[t] += add;
        __syncthreads();
    }
    unsigned total = saux[255];
    unsigned excl = saux[t] - csum;
    if (t == 0 && (int)total <= k) { saux[256] = 4096u; saux[257] = 0u; }
    if ((int)total > k) {
        unsigned cum = excl;
        #pragma unroll
        for (int j = 0; j < 16; j++) {
            unsigned h = shist[t * 16 + j];
            if ((int)cum < k && (int)(cum + h) >= k) {
                saux[256] = (unsigned)(t * 16 + j);
                saux[257] = (unsigned)(k - (int)cum);
            }
            cum += h;
        }
    }
    __syncthreads();
}

// keep k smallest (uniform(key), index) among list[0..n); set kept flags; optional kept list.
__device__ void sel_keep(const int* list, int n, int k, unsigned ka, unsigned kb,
                         unsigned char* kept, int* keptlist,
                         unsigned* shist, unsigned* saux, unsigned long long* sbuf) {
    int t = threadIdx.x;
    if (t == 0) { saux[258] = 0u; saux[259] = 0u; }
    for (int j = t; j < 4096; j += 256) shist[j] = 0u;
    __syncthreads();
    if (n <= k) {
        for (int e = t; e < n; e += 256) {
            int i = list[e];
            kept[i] = 1;
            if (keptlist) keptlist[atomicAdd(&saux[259], 1u)] = i;
        }
        __syncthreads();
        return;
    }
    for (int e = t; e < n; e += 256) {
        unsigned v = rng_v(ka, kb, (unsigned)list[e]);
        atomicAdd(&shist[v >> 11], 1u);
    }
    __syncthreads();
    find_boundary(shist, saux, k);
    int B = (int)saux[256], need = (int)saux[257];
    for (int e = t; e < n; e += 256) {
        int i = list[e];
        unsigned v = rng_v(ka, kb, (unsigned)i);
        int bin = (int)(v >> 11);
        if (bin < B) {
            kept[i] = 1;
            if (keptlist) keptlist[atomicAdd(&saux[259], 1u)] = i;
        } else if (bin == B) {
            unsigned p = atomicAdd(&saux[258], 1u);
            if (p < 512u) sbuf[p] = ((unsigned long long)v << 32) | (unsigned)i;
        }
    }
    __syncthreads();
    int m = (int)saux[258]; if (m > 512) m = 512;
    for (int e = t; e < m; e += 256) {
        unsigned long long key = sbuf[e];
        int rank = 0;
        for (int j = 0; j < m; j++) rank += (sbuf[j] < key);
        if (rank < need) {
            int i = (int)(unsigned)(key & 0xFFFFFFFFu);
            kept[i] = 1;
            if (keptlist) keptlist[atomicAdd(&saux[259], 1u)] = i;
        }
    }
    __syncthreads();
}

// ----------------- the single persistent kernel -----------------
__global__ void __launch_bounds__(TPB, 4)
k_all(const float4* __restrict__ anchors, const float* __restrict__ img,
      const float4* __restrict__ gt, float* __restrict__ out,
      unsigned k1a, unsigned k1b, unsigned k2a, unsigned k2b, unsigned k3a, unsigned k3b) {
    __shared__ float4             sg[NG];
    __shared__ float              sga[NG];
    __shared__ float              sgm[NG];
    __shared__ unsigned           smax[NG];
    __shared__ float              sminb[128];
    __shared__ unsigned           shist[4096];
    __shared__ unsigned           saux[264];
    __shared__ unsigned long long sbuf[512];

    int t = threadIdx.x;
    int gtid = blockIdx.x * TPB + t;
    float H = img[0], W = img[1];

    // ---- P0: init + inside + compact inside list ----
    for (int i = gtid; i < NA; i += NTH) {
        float4 a = anchors[i];
        bool inside = (a.x >= 0.0f) && (a.y >= 0.0f) && (a.z < W) && (a.w < H);
        g_inside[i] = inside ? 1 : 0;
        g_max_ov[i] = -1.0f;
        g_keptA[i] = 0; g_keptF[i] = 0; g_keptB[i] = 0;
        unsigned m = __ballot_sync(0xFFFFFFFFu, inside);
        int lane = t & 31;
        int base = 0;
        if (lane == 0 && m) base = atomicAdd(&g_icount, __popc(m));
        base = __shfl_sync(0xFFFFFFFFu, base, 0);
        if (inside) g_ilist[base + __popc(m & ((1u << lane) - 1u))] = i;
    }
    for (int j = gtid; j < 4096; j += NTH) { g_histbg[j] = 0u; g_bgcnt[j] = 0; }
    if (gtid < NG) g_gtmax_enc[gtid] = 0x407FFFFFu;   // enc(-1.0f)
    if (gtid == 0) { g_ccount = 0; g_candcnt = 0; g_flcnt = 0; }
    // load gt into smem (every block)
    if (t < NG) {
        float4 g = gt[t]; sg[t] = g;
        sga[t] = __fmul_rn(__fadd_rn(__fsub_rn(g.z, g.x), 1.0f),
                           __fadd_rn(__fsub_rn(g.w, g.y), 1.0f));
        smax[t] = 0x407FFFFFu;
    }
    gbar();

    // ---- P1: IoU over compacted inside list; max_ov + gt_max + fg list + bg hist/buckets ----
    {
        int n = g_icount;
        for (int idx = gtid; idx < n; idx += NTH) {
            int i = g_ilist[idx];
            float4 a = anchors[i];
            float areaA = __fmul_rn(__fadd_rn(__fsub_rn(a.z, a.x), 1.0f),
                                    __fadd_rn(__fsub_rn(a.w, a.y), 1.0f));
            float mo = -1.0f;
            #pragma unroll 4
            for (int r = 0; r < NG; r++) {
                float4 g = sg[r];
                float iw = __fadd_rn(__fsub_rn(fminf(a.z, g.z), fmaxf(a.x, g.x)), 1.0f);
                float ih = __fadd_rn(__fsub_rn(fminf(a.w, g.w), fmaxf(a.y, g.y)), 1.0f);
                float inter = __fmul_rn(fmaxf(iw, 0.0f), fmaxf(ih, 0.0f));
                float uni = __fsub_rn(__fadd_rn(areaA, sga[r]), inter);
                float q = __fdiv_rn(inter, uni);
                mo = fmaxf(mo, q);
                unsigned e = __float_as_uint(q) | 0x80000000u;
                if (e > ((volatile unsigned*)smax)[r]) atomicMax(&smax[r], e);
            }
            g_max_ov[i] = mo;
            if (mo >= 0.7f) {
                int slot = atomicAdd(&g_flcnt, 1);
                if (slot < 32768) g_flist[slot] = i;
            }
            if (mo < 0.3f) {
                unsigned v = rng_v(k3a, k3b, (unsigned)i);
                int bin = (int)(v >> 11);
                atomicAdd(&g_histbg[bin], 1u);
                int slot = atomicAdd(&g_bgcnt[bin], 1);
                if (slot < 128) g_bgbuf[bin * 128 + slot] = ((unsigned long long)v << 32) | (unsigned)i;
            }
        }
        __syncthreads();
        if (t < NG) atomicMax(&g_gtmax_enc[t], smax[t]);
    }
    gbar();

    // ---- P2: decode gt_max (smem), min over gts, compact prefilter list ----
    if (t < 128) sminb[t] = (t < NG) ? dec_gtmax(g_gtmax_enc[t]) : 1e30f;
    if (t < NG) sgm[t] = dec_gtmax(g_gtmax_enc[t]);
    __syncthreads();
    for (int o = 64; o > 0; o >>= 1) { if (t < o) sminb[t] = fminf(sminb[t], sminb[t + o]); __syncthreads(); }
    {
        float mn = sminb[0];
        for (int i = gtid; i < NA; i += NTH) {
            bool c = (g_inside[i] != 0) && (g_max_ov[i] >= mn);
            unsigned m = __ballot_sync(0xFFFFFFFFu, c);
            int lane = t & 31;
            int base = 0;
            if (lane == 0 && m) base = atomicAdd(&g_ccount, __popc(m));
            base = __shfl_sync(0xFFFFFFFFu, base, 0);
            if (c) g_clist[base + __popc(m & ((1u << lane) - 1u))] = i;
        }
    }
    gbar();

    // ---- P3: exact tie-set over compacted prefilter list -> candlist ----
    {
        int nc = g_ccount;
        for (int idx = gtid; idx < nc; idx += NTH) {
            int i = g_clist[idx];
            float4 a = anchors[i];
            float areaA = __fmul_rn(__fadd_rn(__fsub_rn(a.z, a.x), 1.0f),
                                    __fadd_rn(__fsub_rn(a.w, a.y), 1.0f));
            bool c = false;
            #pragma unroll 4
            for (int r = 0; r < NG; r++) {
                float4 g = sg[r];
                float iw = __fadd_rn(__fsub_rn(fminf(a.z, g.z), fmaxf(a.x, g.x)), 1.0f);
                float ih = __fadd_rn(__fsub_rn(fminf(a.w, g.w), fmaxf(a.y, g.y)), 1.0f);
                float inter = __fmul_rn(fmaxf(iw, 0.0f), fmaxf(ih, 0.0f));
                float uni = __fsub_rn(__fadd_rn(areaA, sga[r]), inter);
                float q = __fdiv_rn(inter, uni);
                if (q == sgm[r]) c = true;
            }
            if (c) {
                int slot = atomicAdd(&g_candcnt, 1);
                if (slot < 8192) g_candlist[slot] = i;
            }
        }
    }
    gbar();

    // ---- P4: block 0 does all three subsamplings ----
    if (blockIdx.x == 0) {
        // selection A: keep_at_most(cand, R=100, k1)
        int nc = g_candcnt; if (nc > 8192) nc = 8192;
        sel_keep(g_candlist, nc, NG, k1a, k1b, g_keptA, g_kalist, shist, saux, sbuf);
        int nka = (nc <= NG) ? nc : NG;
        // fg list = flist (mo>=0.7) + keptA with mo<0.7
        int nf0 = g_flcnt; if (nf0 > 32768) nf0 = 32768;
        if (t == 0) saux[261] = 0u;
        __syncthreads();
        for (int e = t; e < nka; e += 256) {
            int i = g_kalist[e];
            if (g_max_ov[i] < 0.7f) {
                int slot = nf0 + (int)atomicAdd(&saux[261], 1u);
                if (slot < 32768) g_flist[slot] = i;
            }
        }
        __syncthreads();
        int nf = nf0 + (int)saux[261]; if (nf > 32768) nf = 32768;
        // selection F: keep_at_most(fg, 128, k2)
        sel_keep(g_flist, nf, 128, k2a, k2b, g_keptF, 0, shist, saux, sbuf);
        int n_fg = (nf < 128) ? nf : 128;
        // bg: hist over (inside & mo<0.3) minus keptA members
        for (int j = t; j < 4096; j += 256) shist[j] = g_histbg[j];
        __syncthreads();
        for (int e = t; e < nka; e += 256) {
            int i = g_kalist[e];
            if (g_max_ov[i] < 0.3f) {
                unsigned v = rng_v(k3a, k3b, (unsigned)i);
                atomicSub(&shist[v >> 11], 1u);
            }
        }
        __syncthreads();
        find_boundary(shist, saux, 256 - n_fg);
        int Bb = (int)saux[256], need = (int)saux[257];
        if (t == 0) g_bgB = Bb;
        if (Bb < 4096) {
            if (t == 0) saux[258] = 0u;
            __syncthreads();
            int m = g_bgcnt[Bb]; if (m > 128) m = 128;
            for (int e = t; e < m; e += 256) {
                unsigned long long ent = g_bgbuf[Bb * 128 + e];
                int i = (int)(unsigned)(ent & 0xFFFFFFFFu);
                if (!g_keptA[i]) sbuf[atomicAdd(&saux[258], 1u)] = ent;
            }
            __syncthreads();
            int mm = (int)saux[258];
            for (int e = t; e < mm; e += 256) {
                unsigned long long key = sbuf[e];
                int rank = 0;
                for (int j = 0; j < mm; j++) rank += (sbuf[j] < key);
                if (rank < need) g_keptB[(unsigned)(key & 0xFFFFFFFFu)] = 1;
            }
        }
    }
    gbar();

    // ---- P5: final labels + bbox targets ----
    {
        int Bb = g_bgB;
        for (int i = gtid; i < NA; i += NTH) {
            float mo = g_max_ov[i];
            bool inside = g_inside[i] != 0;
            float lab = -1.0f;
            if (inside) {
                if (mo < 0.3f) lab = 0.0f;
                if (g_keptA[i]) lab = 1.0f;
                if (mo >= 0.7f) lab = 1.0f;
                if (lab == 1.0f && !g_keptF[i]) lab = -1.0f;
                if (lab == 0.0f) {
                    unsigned v = rng_v(k3a, k3b, (unsigned)i);
                    bool keep = ((int)(v >> 11) < Bb) || g_keptB[i];
                    if (!keep) lab = -1.0f;
                }
            }
            out[i] = lab;

            int idx = __float2int_rz(mo);
            idx = max(0, min(idx, NG - 1));
            float4 g = sg[idx];
            float4 a = anchors[i];
            float o0 = 0.0f, o1 = 0.0f, o2 = 0.0f, o3 = 0.0f;
            if (inside) {
                float aw = a.z - a.x + 1.0f, ah = a.w - a.y + 1.0f;
                float acx = a.x + 0.5f * aw, acy = a.y + 0.5f * ah;
                float gw = g.z - g.x + 1.0f, gh = g.w - g.y + 1.0f;
                float gcx = g.x + 0.5f * gw, gcy = g.y + 0.5f * gh;
                o0 = (gcx - acx) / aw;
                o1 = (gcy - acy) / ah;
                o2 = logf(gw / aw);
                o3 = logf(gh / ah);
            }
            float* tp = out + NA + 4 * i;
            tp[0] = o0; tp[1] = o1; tp[2] = o2; tp[3] = o3;
        }
    }
    // reset the inside-list counter for the next replay (after use, before exit)
    gbar();
    if (gtid == 0) g_icount = 0;
}

// ----------------- launch -----------------
extern "C" void kernel_launch(void* const* d_in, const int* in_sizes, int n_in,
                              void* d_out, int out_size) {
    const float4* anchors = (const float4*)d_in[0];
    const float*  img     = (const float*)d_in[1];
    const float4* gt      = (const float4*)d_in[2];
    float* out = (float*)d_out;

    // jax.random.key(42) -> (0,42); split via partitionable path:
    // key_i = threefry2x32((0,42), (hi=0, lo=i))
    unsigned ks[3][2];
    for (unsigned i = 0; i < 3; i++) tf2x32(0u, 42u, 0u, i, ks[i][0], ks[i][1]);

    k_all<<<GRID, TPB>>>(anchors, img, gt, out,
                         ks[0][0], ks[0][1], ks[1][0], ks[1][1], ks[2][0], ks[2][1]);
}